// round 6
// baseline (speedup 1.0000x reference)
#include <cuda_runtime.h>
#include <cuda_fp16.h>
#include <cstdint>

typedef unsigned long long u64;
typedef unsigned int u32;

#define NPTS    6144
#define JSPLIT  12
#define IBLK    (NPTS / 256)          // 24 i-blocks (256 rows each)
#define KSTEPS  (NPTS / 16)           // 384 total k-steps (16 j each)
#define KSPB    (KSTEPS / JSPLIT)     // 32 k-steps per block
#define KS_STAGE 8
#define NSTAGE  (KSPB / KS_STAGE)     // 4
#define NMOM    24                    // moment columns (21 used)

// ---------------- device scratch ----------------
// per-j: {cx*L2E dup, cz*L2E dup, ct*L2E dup, -0.5|c|^2*L2E dup}
__device__ u64 g_cpk[NPTS * 4];
// B fragments: [ks][term(hi/lo)][n(0..2)][lane] u64 = {b0, b1} f16x2 regs
__device__ u64 g_Bf[KSTEPS * 2 * 3 * 32];
// moment partials: [JSPLIT][NPTS][NMOM]
__device__ float g_part[JSPLIT * NPTS * NMOM];

// ---------------- helpers ----------------
__device__ __forceinline__ u32 smem_u32(const void* p) {
    u32 a; asm("{ .reg .u64 t; cvta.to.shared.u64 t, %1; cvt.u32.u64 %0, t; }" : "=r"(a) : "l"(p));
    return a;
}
__device__ __forceinline__ u64 pk2(float lo, float hi) {
    u64 r; asm("mov.b64 %0, {%1, %2};" : "=l"(r) : "f"(lo), "f"(hi)); return r;
}
__device__ __forceinline__ void upk2(u64 v, float& lo, float& hi) {
    asm("mov.b64 {%0, %1}, %2;" : "=f"(lo), "=f"(hi) : "l"(v));
}
__device__ __forceinline__ u64 fma2(u64 a, u64 b, u64 c) {
    u64 d; asm("fma.rn.f32x2 %0, %1, %2, %3;" : "=l"(d) : "l"(a), "l"(b), "l"(c)); return d;
}
__device__ __forceinline__ float ex2f(float a) {
    float r; asm("ex2.approx.ftz.f32 %0, %1;" : "=f"(r) : "f"(a)); return r;
}
// pack two f32 -> f16x2 (first arg in low 16 bits)
__device__ __forceinline__ u32 f16pk(float lo, float hi) {
    u32 d; asm("cvt.rn.f16x2.f32 %0, %1, %2;" : "=r"(d) : "f"(hi), "f"(lo)); return d;
}
__device__ __forceinline__ void cpa16(u32 saddr, const void* g) {
    asm volatile("cp.async.cg.shared.global [%0], [%1], 16;" :: "r"(saddr), "l"(g));
}
__device__ __forceinline__ void cpa_commit() { asm volatile("cp.async.commit_group;" ::: "memory"); }
template <int N> __device__ __forceinline__ void cpa_wait() {
    asm volatile("cp.async.wait_group %0;" :: "n"(N) : "memory");
}
__device__ __forceinline__ void mma_f16(float* c, const u32* a, const u32* b) {
    asm volatile(
        "mma.sync.aligned.m16n8k16.row.col.f32.f16.f16.f32 "
        "{%0,%1,%2,%3}, {%4,%5,%6,%7}, {%8,%9}, {%0,%1,%2,%3};"
        : "+f"(c[0]), "+f"(c[1]), "+f"(c[2]), "+f"(c[3])
        : "r"(a[0]), "r"(a[1]), "r"(a[2]), "r"(a[3]), "r"(b[0]), "r"(b[1]));
}

// ---------------- prep: smem-staged, 1 block per 128-j chunk ----------------
__global__ __launch_bounds__(256) void prep_all(
    const float* __restrict__ c,
    const float* __restrict__ v1, const float* __restrict__ v2,
    const float* __restrict__ v3, const float* __restrict__ v4)
{
    __shared__ float scx[128], scz[128], sct[128];
    __shared__ float sv[4][128];

    const int tid = threadIdx.x;
    const int j0  = blockIdx.x * 128;

    // coalesced stage of c (384 floats) and v1..v4 (512 floats)
    for (int q = tid; q < 384; q += 256) {
        const float val = c[j0 * 3 + q];
        const int j = q / 3, r = q - 3 * j;
        if (r == 0) scx[j] = val; else if (r == 1) scz[j] = val; else sct[j] = val;
    }
    for (int q = tid; q < 512; q += 256) {
        const int vi = q >> 7, jj = q & 127;
        const float* vp = (vi == 0) ? v1 : (vi == 1) ? v2 : (vi == 2) ? v3 : v4;
        sv[vi][jj] = vp[j0 + jj];
    }
    __syncthreads();

    // part 1: per-j A-side constants (128 j per block)
    if (tid < 128) {
        const int j = j0 + tid;
        const float L2E = 1.4426950408889634f;
        const float cx = scx[tid], cz = scz[tid], ct = sct[tid];
        const float kc = -0.5f * (cx * cx + cz * cz + ct * ct) * L2E;
        g_cpk[j * 4 + 0] = pk2(cx * L2E, cx * L2E);
        g_cpk[j * 4 + 1] = pk2(cz * L2E, cz * L2E);
        g_cpk[j * 4 + 2] = pk2(ct * L2E, ct * L2E);
        g_cpk[j * 4 + 3] = pk2(kc, kc);
    }

    // part 2: B fragments — 8 k-steps x 96 lanes = 768 tasks per block
    for (int task = tid; task < 768; task += 256) {
        const int lane = task & 31;
        const int n    = (task >> 5) % 3;
        const int ksl  = task / 96;                 // local k-step 0..7
        const int ks   = blockIdx.x * 8 + ksl;
        const int cc   = lane & 3, g = lane >> 2;
        const int m    = n * 8 + g;

        float u[4];
#pragma unroll
        for (int q = 0; q < 4; q++) {
            const int jl = ksl * 16 + 2 * cc + (q & 1) + ((q >> 1) << 3);  // local j
            float val = 0.0f;
            if (m < 21) {
                const float cx = scx[jl], cz = scz[jl], ct = sct[jl];
                float vv, base;
                int r6;
                if (m < 3) { vv = sv[0][jl]; r6 = m; }
                else {
                    const int g2 = (m - 3) / 6;
                    vv = sv[1 + g2][jl];
                    r6 = (m - 3) % 6;
                }
                base = (r6 == 0) ? 1.0f : (r6 == 1) ? cx : (r6 == 2) ? cz :
                       (r6 == 3) ? ct   : (r6 == 4) ? cx * cx : cz * cz;
                val = base * vv;
            }
            u[q] = val;
        }
        // fp16 split: hi = rn(u); lo = rn(u - hi)
        const u32 b0h = f16pk(u[0], u[1]);
        const u32 b1h = f16pk(u[2], u[3]);
        const float h00 = __half2float(__ushort_as_half((unsigned short)(b0h & 0xFFFFu)));
        const float h01 = __half2float(__ushort_as_half((unsigned short)(b0h >> 16)));
        const float h10 = __half2float(__ushort_as_half((unsigned short)(b1h & 0xFFFFu)));
        const float h11 = __half2float(__ushort_as_half((unsigned short)(b1h >> 16)));
        const u32 b0l = f16pk(u[0] - h00, u[1] - h01);
        const u32 b1l = f16pk(u[2] - h10, u[3] - h11);
        g_Bf[(ks * 2 + 0) * 96 + n * 32 + lane] = ((u64)b1h << 32) | b0h;
        g_Bf[(ks * 2 + 1) * 96 + n * 32 + lane] = ((u64)b1l << 32) | b0l;
    }
}

// ---------------- main: fused exp + fp16 2-term moment GEMM ----------------
__global__ __launch_bounds__(256, 2) void rbf_mma(
    const float* __restrict__ x, const float* __restrict__ z, const float* __restrict__ t)
{
    __shared__ __align__(16) char sB[2][KS_STAGE * 1536];   // 2 x 12KB
    __shared__ __align__(16) char sC[2][KS_STAGE * 512];    // 2 x 4KB

    const int tid  = threadIdx.x;
    const int w    = tid >> 5, lane = tid & 31;
    const int r    = lane >> 2, cc = lane & 3;
    const int ib   = blockIdx.x, js = blockIdx.y;
    const int i0   = ib * 256 + w * 32;

    const u64 xp0 = pk2(x[i0 + r], x[i0 + r + 8]);
    const u64 xp1 = pk2(x[i0 + r + 16], x[i0 + r + 24]);
    const u64 zp0 = pk2(z[i0 + r], z[i0 + r + 8]);
    const u64 zp1 = pk2(z[i0 + r + 16], z[i0 + r + 24]);
    const u64 tp0 = pk2(t[i0 + r], t[i0 + r + 8]);
    const u64 tp1 = pk2(t[i0 + r + 16], t[i0 + r + 24]);

    float acc[2][3][4];
#pragma unroll
    for (int a = 0; a < 2; a++)
#pragma unroll
        for (int b = 0; b < 3; b++)
#pragma unroll
            for (int q = 0; q < 4; q++) acc[a][b][q] = 0.0f;

    const int ks0 = js * KSPB;
    const char* gB = (const char*)g_Bf + (u64)ks0 * 1536;
    const char* gC = (const char*)g_cpk + (u64)ks0 * 512;

    // prologue prefetch stage 0
    {
        u32 dB = smem_u32(&sB[0][0]);
#pragma unroll
        for (int q = 0; q < 3; q++) cpa16(dB + tid * 16 + q * 4096, gB + tid * 16 + q * 4096);
        cpa16(smem_u32(&sC[0][0]) + tid * 16, gC + tid * 16);
        cpa_commit();
    }

    for (int st = 0; st < NSTAGE; st++) {
        const int buf = st & 1;
        if (st + 1 < NSTAGE) {
            const int nb = buf ^ 1;
            u32 dB = smem_u32(&sB[nb][0]);
            const char* sBg = gB + (u64)(st + 1) * (KS_STAGE * 1536);
#pragma unroll
            for (int q = 0; q < 3; q++) cpa16(dB + tid * 16 + q * 4096, sBg + tid * 16 + q * 4096);
            cpa16(smem_u32(&sC[nb][0]) + tid * 16, gC + (u64)(st + 1) * (KS_STAGE * 512) + tid * 16);
            cpa_commit();
            cpa_wait<1>();
        } else {
            cpa_wait<0>();
        }
        __syncthreads();

#pragma unroll 1
        for (int k = 0; k < KS_STAGE; k++) {
            // ---- A side: 16 G' values, fp16 single precision ----
            float G0[4], G1[4], G2[4], G3[4];
#pragma unroll
            for (int jj = 0; jj < 4; jj++) {
                const int jloc = 2 * cc + (jj & 1) + ((jj >> 1) << 3);
                const char* cp = &sC[buf][k * 512 + jloc * 32];
                const ulonglong2 q0 = *(const ulonglong2*)cp;
                const ulonglong2 q1 = *(const ulonglong2*)(cp + 16);
                u64 d0 = fma2(q1.x, tp0, q1.y);
                d0 = fma2(q0.y, zp0, d0);
                d0 = fma2(q0.x, xp0, d0);
                u64 d1 = fma2(q1.x, tp1, q1.y);
                d1 = fma2(q0.y, zp1, d1);
                d1 = fma2(q0.x, xp1, d1);
                float f0, f1, f2, f3; upk2(d0, f0, f1); upk2(d1, f2, f3);
                G0[jj] = ex2f(f0); G1[jj] = ex2f(f1);
                G2[jj] = ex2f(f2); G3[jj] = ex2f(f3);
            }
            u32 ah[2][4];
            ah[0][0] = f16pk(G0[0], G0[1]);
            ah[0][1] = f16pk(G1[0], G1[1]);
            ah[0][2] = f16pk(G0[2], G0[3]);
            ah[0][3] = f16pk(G1[2], G1[3]);
            ah[1][0] = f16pk(G2[0], G2[1]);
            ah[1][1] = f16pk(G3[0], G3[1]);
            ah[1][2] = f16pk(G2[2], G2[3]);
            ah[1][3] = f16pk(G3[2], G3[3]);

            // ---- B frags (hi + lo) ----
            u32 bh[3][2], bl[3][2];
            const char* bp = &sB[buf][k * 1536 + lane * 8];
#pragma unroll
            for (int n = 0; n < 3; n++) {
                const uint2 vh = *(const uint2*)(bp + n * 256);
                const uint2 vl = *(const uint2*)(bp + 768 + n * 256);
                bh[n][0] = vh.x; bh[n][1] = vh.y;
                bl[n][0] = vl.x; bl[n][1] = vl.y;
            }

            // ---- 12 MMAs: a*bh + a*bl ----
#pragma unroll
            for (int mt = 0; mt < 2; mt++)
#pragma unroll
                for (int n = 0; n < 3; n++) {
                    mma_f16(acc[mt][n], ah[mt], bh[n]);
                    mma_f16(acc[mt][n], ah[mt], bl[n]);
                }
        }
        __syncthreads();
    }

    // ---- write moment partials ----
#pragma unroll
    for (int mt = 0; mt < 2; mt++)
#pragma unroll
        for (int n = 0; n < 3; n++) {
            const int row = i0 + mt * 16 + r;
            const int col = n * 8 + 2 * cc;
            float2* d0 = (float2*)&g_part[((u64)js * NPTS + row) * NMOM + col];
            float2* d1 = (float2*)&g_part[((u64)js * NPTS + row + 8) * NMOM + col];
            *d0 = make_float2(acc[mt][n][0], acc[mt][n][1]);
            *d1 = make_float2(acc[mt][n][2], acc[mt][n][3]);
        }
}

// ---------------- epilogue: reduce splits + apply e^{-.5|p|^2} + combos ----------------
__global__ void rbf_epi(const float* __restrict__ x, const float* __restrict__ z,
                        const float* __restrict__ t, float* __restrict__ out)
{
    const int i = blockIdx.x * blockDim.x + threadIdx.x;
    if (i >= NPTS) return;
    float S[NMOM];
#pragma unroll
    for (int m = 0; m < NMOM; m++) S[m] = 0.0f;
#pragma unroll
    for (int js = 0; js < JSPLIT; js++) {
        const float4* p = (const float4*)&g_part[((u64)js * NPTS + i) * NMOM];
#pragma unroll
        for (int q = 0; q < 6; q++) {
            const float4 v = p[q];
            S[q * 4 + 0] += v.x; S[q * 4 + 1] += v.y;
            S[q * 4 + 2] += v.z; S[q * 4 + 3] += v.w;
        }
    }
    const float xi = x[i], zi = z[i], ti = t[i];
    const float ep = __expf(-0.5f * (xi * xi + zi * zi + ti * ti));
#pragma unroll
    for (int m = 0; m < 21; m++) S[m] *= ep;
    const float xx = xi * xi - 1.0f, zz = zi * zi - 1.0f;

    out[0  * NPTS + i] = S[10] - xi * S[9];
    out[1  * NPTS + i] = S[11] - zi * S[9];
    out[2  * NPTS + i] = S[12] - ti * S[9];
    out[3  * NPTS + i] = S[16] - xi * S[15];
    out[4  * NPTS + i] = S[17] - zi * S[15];
    out[5  * NPTS + i] = S[18] - ti * S[15];
    out[6  * NPTS + i] = S[4]  - xi * S[3];
    out[7  * NPTS + i] = S[5]  - zi * S[3];
    out[8  * NPTS + i] = S[6]  - ti * S[3];
    out[9  * NPTS + i] = S[1]  - xi * S[0];
    out[10 * NPTS + i] = S[2]  - zi * S[0];
    out[11 * NPTS + i] = S[13] - 2.0f * xi * S[10] + xx * S[9];
    out[12 * NPTS + i] = S[14] - 2.0f * zi * S[11] + zz * S[9];
    out[13 * NPTS + i] = S[19] - 2.0f * xi * S[16] + xx * S[15];
    out[14 * NPTS + i] = S[20] - 2.0f * zi * S[17] + zz * S[15];
    out[15 * NPTS + i] = S[7]  - 2.0f * xi * S[4]  + xx * S[3];
    out[16 * NPTS + i] = S[8]  - 2.0f * zi * S[5]  + zz * S[3];
}

extern "C" void kernel_launch(void* const* d_in, const int* in_sizes, int n_in,
                              void* d_out, int out_size)
{
    const float* x  = (const float*)d_in[0];
    const float* z  = (const float*)d_in[1];
    const float* t  = (const float*)d_in[2];
    const float* c  = (const float*)d_in[3];
    const float* v1 = (const float*)d_in[4];
    const float* v2 = (const float*)d_in[5];
    const float* v3 = (const float*)d_in[6];
    const float* v4 = (const float*)d_in[7];

    prep_all<<<NPTS / 128, 256>>>(c, v1, v2, v3, v4);     // 48 blocks, smem-staged

    dim3 grid(IBLK, JSPLIT);                 // (24, 12) = 288 blocks
    rbf_mma<<<grid, 256>>>(x, z, t);

    rbf_epi<<<NPTS / 32, 32>>>(x, z, t, (float*)d_out);   // 192 blocks, full-chip
}